// round 4
// baseline (speedup 1.0000x reference)
#include <cuda_runtime.h>
#include <cuda_bf16.h>

// MixingBlock restructured:
//   M[b] = scale * Wq @ (slot[b]@Wk)^T   [180 x 32] per batch
//   dots[b,r,:] = x[b,r,:] @ M[b] ; w = softmax(dots); s = w @ slot[b]
// All fp32, packed f32x2 FMA (Blackwell FFMA2) in hot loops.
// Phase 3 keeps slot columns in REGISTERS (per-lane v[32]) and reads w via
// broadcast-only LDS -> minimal L1 wavefronts, zero syncs in the loop.

#define BB 4
#define RR 8192
#define SS 32
#define IN_DIM 180
#define SLOT_DIM 1536
#define ATT_DIM 1536
#define KSPLIT 8                  // gemm1 split over slot_dim reduction
#define KC (SLOT_DIM / KSPLIT)    // 192
#define TILE_R 64

typedef unsigned long long u64;

__device__ __forceinline__ u64 fma2(u64 a, u64 b, u64 c) {
    u64 d;
    asm("fma.rn.f32x2 %0, %1, %2, %3;" : "=l"(d) : "l"(a), "l"(b), "l"(c));
    return d;
}
__device__ __forceinline__ u64 pk2(float v) {
    u64 r;
    asm("mov.b64 %0, {%1, %1};" : "=l"(r) : "r"(__float_as_uint(v)));
    return r;
}

// Scratch
__device__ float g_kpart[KSPLIT * BB * ATT_DIM * SS];  // [p][b][a][s]
__device__ float g_ksum[BB * ATT_DIM * SS];            // [b][a][s]
__device__ float g_M[BB * IN_DIM * SS];                // [b][i][s], scale applied

// ---------------------------------------------------------------------------
// GEMM1: g_kpart[p][b][a][s] = sum_{j in chunk p} slot[b][s][j] * Wk[j][a]
// Grid (12, 4, 8) = 384 blocks, 256 threads, f32x2 microtile 4r x 4c.
// ---------------------------------------------------------------------------
__global__ __launch_bounds__(256) void gemm1_kernel(const float* __restrict__ slot,
                                                    const float* __restrict__ Wk) {
    __shared__ float As[32 * 36];   // [s][k], stride 36
    __shared__ float Bs[32 * 128];  // [k][c]
    int t = threadIdx.x;
    int warp = t >> 5, lane = t & 31;
    int a0 = blockIdx.x * 128;
    int b  = blockIdx.y;
    int p  = blockIdx.z;
    int j_base = p * KC;

    u64 acc[4][2] = {};
    for (int jc = 0; jc < KC / 32; jc++) {
        int j0 = j_base + jc * 32;
        {   // stage A: 32 s x 32 j
            int s_l = t >> 3, k4 = (t & 7) << 2;
            float4 v = *reinterpret_cast<const float4*>(
                &slot[(size_t)(b * SS + s_l) * SLOT_DIM + j0 + k4]);
            *reinterpret_cast<float4*>(&As[s_l * 36 + k4]) = v;
        }
        {   // stage B: 32 j x 128 a
            int k = t >> 3, cb = (t & 7) << 2;
            const float* src = &Wk[(size_t)(j0 + k) * ATT_DIM + a0];
            #pragma unroll
            for (int cc = 0; cc < 4; cc++) {
                int c = cb + cc * 32;
                *reinterpret_cast<float4*>(&Bs[k * 128 + c]) =
                    *reinterpret_cast<const float4*>(&src[c]);
            }
        }
        __syncthreads();
        #pragma unroll 8
        for (int k = 0; k < 32; k++) {
            ulonglong2 bv = *reinterpret_cast<const ulonglong2*>(&Bs[k * 128 + lane * 4]);
            #pragma unroll
            for (int ri = 0; ri < 4; ri++) {
                u64 a2 = pk2(As[(4 * warp + ri) * 36 + k]);
                acc[ri][0] = fma2(a2, bv.x, acc[ri][0]);
                acc[ri][1] = fma2(a2, bv.y, acc[ri][1]);
            }
        }
        __syncthreads();
    }
    float* dst = &g_kpart[((size_t)(p * BB + b) * ATT_DIM + a0) * SS];
    #pragma unroll
    for (int ri = 0; ri < 4; ri++) {
        #pragma unroll
        for (int cj = 0; cj < 2; cj++) {
            float lo = __uint_as_float((unsigned)(acc[ri][cj] & 0xffffffffu));
            float hi = __uint_as_float((unsigned)(acc[ri][cj] >> 32));
            dst[(lane * 4 + 2 * cj + 0) * SS + 4 * warp + ri] = lo;
            dst[(lane * 4 + 2 * cj + 1) * SS + 4 * warp + ri] = hi;
        }
    }
}

// ---------------------------------------------------------------------------
// Reduce: g_ksum = sum_p g_kpart
// ---------------------------------------------------------------------------
__global__ __launch_bounds__(256) void reducek_kernel() {
    int idx = blockIdx.x * 256 + threadIdx.x;  // float4 index over 49152
    const float4* src = reinterpret_cast<const float4*>(g_kpart);
    float4 a = src[idx];
    #pragma unroll
    for (int p = 1; p < KSPLIT; p++) {
        float4 v = src[(size_t)p * (BB * ATT_DIM * SS / 4) + idx];
        a.x += v.x; a.y += v.y; a.z += v.z; a.w += v.w;
    }
    reinterpret_cast<float4*>(g_ksum)[idx] = a;
}

// ---------------------------------------------------------------------------
// GEMM2: g_M[b][i][s] = scale * sum_a Wq[i][a] * g_ksum[b][a][s]
// Grid (23, 4), 256 threads; warp owns one i, lanes own s. Full K=1536.
// ---------------------------------------------------------------------------
__global__ __launch_bounds__(256) void gemm2_kernel(const float* __restrict__ Wq) {
    __shared__ float ks[64 * 32];
    int t = threadIdx.x;
    int warp = t >> 5, lane = t & 31;
    int b = blockIdx.y;
    int i = blockIdx.x * 8 + warp;
    const float* kp = &g_ksum[(size_t)b * ATT_DIM * SS];
    float acc = 0.f;
    for (int a0 = 0; a0 < ATT_DIM; a0 += 64) {
        __syncthreads();
        #pragma unroll
        for (int v = 0; v < 2; v++) {
            int lin = (t + v * 256) * 4;
            *reinterpret_cast<float4*>(&ks[lin]) =
                *reinterpret_cast<const float4*>(&kp[(size_t)a0 * SS + lin]);
        }
        __syncthreads();
        if (i < IN_DIM) {
            const float* wr = &Wq[(size_t)i * ATT_DIM + a0];
            #pragma unroll
            for (int aa = 0; aa < 64; aa += 4) {
                float4 w4 = *reinterpret_cast<const float4*>(&wr[aa]);
                acc += w4.x * ks[(aa + 0) * 32 + lane];
                acc += w4.y * ks[(aa + 1) * 32 + lane];
                acc += w4.z * ks[(aa + 2) * 32 + lane];
                acc += w4.w * ks[(aa + 3) * 32 + lane];
            }
        }
    }
    if (i < IN_DIM)
        g_M[((size_t)b * IN_DIM + i) * SS + lane] = acc * rsqrtf((float)ATT_DIM);
}

// ---------------------------------------------------------------------------
// Fused: dots = x@M -> softmax -> s = w@slot.  64 rows/block, 256 thr.
// Static smem (47616 B):
//   [0, 16384)      u64 w2t[32][64]   packed (w,w), transposed [s][r]
//   [16384, 39424)  float Ms[180][32]
//   [39424, 47616)  float dots[64][32]
// Phase 3: warp x dt owns 64 cols; lane holds v[32] (2 cols x 32 slots) in regs.
// ---------------------------------------------------------------------------
__global__ __launch_bounds__(256, 2) void fused_kernel(const float* __restrict__ x,
                                                       const float* __restrict__ slot,
                                                       float* __restrict__ out_s,
                                                       float* __restrict__ out_w) {
    __shared__ __align__(16) char smraw[47616];
    u64*   w2t    = reinterpret_cast<u64*>(smraw);            // [s][64]
    float* Ms     = reinterpret_cast<float*>(smraw + 16384);  // [i][32]
    float* dots_s = reinterpret_cast<float*>(smraw + 39424);  // [r][32]

    int t = threadIdx.x;
    int warp = t >> 5, lane = t & 31;
    int r0 = blockIdx.x * TILE_R;
    int b  = blockIdx.y;

    // Load M[b] (scale pre-applied)
    for (int idx = t; idx < IN_DIM * SS; idx += 256)
        Ms[idx] = g_M[(size_t)b * IN_DIM * SS + idx];
    __syncthreads();

    // phase 1: dots; thread owns 1 row x 8 s.  4 threads share a row (x-load
    // is 4-way broadcast -> ~8 lines per LDG.128).
    {
        int sg = (t & 3) * 8;
        int r  = t >> 2;
        const float* xrow = &x[(size_t)(b * RR + r0 + r) * IN_DIM];
        u64 d2[4] = {0ull, 0ull, 0ull, 0ull};
        #pragma unroll 3
        for (int i4 = 0; i4 < IN_DIM / 4; i4++) {
            float4 xv = *reinterpret_cast<const float4*>(&xrow[i4 * 4]);
            const float* xc = reinterpret_cast<const float*>(&xv);
            #pragma unroll
            for (int c = 0; c < 4; c++) {
                int i = i4 * 4 + c;
                ulonglong2 m01 = *reinterpret_cast<const ulonglong2*>(&Ms[i * SS + sg]);
                ulonglong2 m23 = *reinterpret_cast<const ulonglong2*>(&Ms[i * SS + sg + 4]);
                u64 xp = pk2(xc[c]);
                d2[0] = fma2(xp, m01.x, d2[0]);
                d2[1] = fma2(xp, m01.y, d2[1]);
                d2[2] = fma2(xp, m23.x, d2[2]);
                d2[3] = fma2(xp, m23.y, d2[3]);
            }
        }
        ulonglong2 o0; o0.x = d2[0]; o0.y = d2[1];
        ulonglong2 o1; o1.x = d2[2]; o1.y = d2[3];
        *reinterpret_cast<ulonglong2*>(&dots_s[r * SS + sg]) = o0;
        *reinterpret_cast<ulonglong2*>(&dots_s[r * SS + sg + 4]) = o1;
    }
    __syncthreads();

    // phase 2: softmax; thread owns 1 row x 8 s, reduce over 4-lane groups.
    {
        int r = t >> 2;
        int sg = (t & 3) * 8;
        float v[8];
        float4 a0 = *reinterpret_cast<const float4*>(&dots_s[r * SS + sg]);
        float4 a1 = *reinterpret_cast<const float4*>(&dots_s[r * SS + sg + 4]);
        v[0] = a0.x; v[1] = a0.y; v[2] = a0.z; v[3] = a0.w;
        v[4] = a1.x; v[5] = a1.y; v[6] = a1.z; v[7] = a1.w;
        float mx = v[0];
        #pragma unroll
        for (int k = 1; k < 8; k++) mx = fmaxf(mx, v[k]);
        mx = fmaxf(mx, __shfl_xor_sync(0xffffffffu, mx, 1));
        mx = fmaxf(mx, __shfl_xor_sync(0xffffffffu, mx, 2));
        float sum = 0.f;
        #pragma unroll
        for (int k = 0; k < 8; k++) { v[k] = __expf(v[k] - mx); sum += v[k]; }
        sum += __shfl_xor_sync(0xffffffffu, sum, 1);
        sum += __shfl_xor_sync(0xffffffffu, sum, 2);
        float inv = 1.0f / sum;
        #pragma unroll
        for (int k = 0; k < 8; k++) v[k] *= inv;
        float* wp = &out_w[(size_t)(b * RR + r0 + r) * SS + sg];
        *reinterpret_cast<float4*>(&wp[0]) = make_float4(v[0], v[1], v[2], v[3]);
        *reinterpret_cast<float4*>(&wp[4]) = make_float4(v[4], v[5], v[6], v[7]);
        #pragma unroll
        for (int k = 0; k < 8; k++)
            w2t[(sg + k) * TILE_R + r] = pk2(v[k]);
    }
    __syncthreads();

    // phase 3: s = w @ slot.  (warp, dt) owns 64 cols; lane owns 2 cols.
    // v[32] in registers; w via broadcast LDS.128; no smem staging, no syncs.
    for (int dt = 0; dt < SLOT_DIM / 512; dt++) {
        int c = dt * 512 + warp * 64 + 2 * lane;
        const float* vsrc = &slot[(size_t)b * SS * SLOT_DIM + c];
        u64 v[SS];
        #pragma unroll
        for (int s = 0; s < SS; s++)
            v[s] = *reinterpret_cast<const u64*>(&vsrc[(size_t)s * SLOT_DIM]);
        #pragma unroll 2
        for (int rg = 0; rg < TILE_R / 4; rg++) {
            u64 a0 = 0ull, a1 = 0ull, a2 = 0ull, a3 = 0ull;
            const u64* wb = &w2t[rg * 4];
            #pragma unroll
            for (int s = 0; s < SS; s++) {
                ulonglong2 w01 = *reinterpret_cast<const ulonglong2*>(&wb[s * TILE_R]);
                ulonglong2 w23 = *reinterpret_cast<const ulonglong2*>(&wb[s * TILE_R + 2]);
                a0 = fma2(w01.x, v[s], a0);
                a1 = fma2(w01.y, v[s], a1);
                a2 = fma2(w23.x, v[s], a2);
                a3 = fma2(w23.y, v[s], a3);
            }
            float* orow = &out_s[(size_t)(b * RR + r0 + rg * 4) * SLOT_DIM + c];
            *reinterpret_cast<u64*>(&orow[0])                      = a0;
            *reinterpret_cast<u64*>(&orow[1 * SLOT_DIM])           = a1;
            *reinterpret_cast<u64*>(&orow[2 * SLOT_DIM])           = a2;
            *reinterpret_cast<u64*>(&orow[3 * SLOT_DIM])           = a3;
        }
    }
}

// ---------------------------------------------------------------------------
extern "C" void kernel_launch(void* const* d_in, const int* in_sizes, int n_in,
                              void* d_out, int out_size) {
    const float* x    = (const float*)d_in[0];  // [4, 8192, 180]
    const float* slot = (const float*)d_in[1];  // [4, 32, 1536]
    const float* Wq   = (const float*)d_in[2];  // [180, 1536]
    const float* Wk   = (const float*)d_in[3];  // [1536, 1536]
    float* out_s = (float*)d_out;                        // [4, 8192, 1536]
    float* out_w = out_s + (size_t)BB * RR * ATT_DIM;    // [4, 8192, 32]

    gemm1_kernel<<<dim3(ATT_DIM / 128, BB, KSPLIT), 256>>>(slot, Wk);
    reducek_kernel<<<(BB * ATT_DIM * SS / 4) / 256, 256>>>();
    gemm2_kernel<<<dim3((IN_DIM + 7) / 8, BB), 256>>>(Wq);
    fused_kernel<<<dim3(RR / TILE_R, BB), 256>>>(x, slot, out_s, out_w);
}